// round 3
// baseline (speedup 1.0000x reference)
#include <cuda_runtime.h>
#include <cstdint>

#define IN_F   4096
#define OUT_F  4096
#define NTHREADS 256

__global__ __launch_bounds__(NTHREADS)
void unary_linear_kernel(
    const float* __restrict__ x,          // [1, IN_F]
    const float* __restrict__ buf_wght,   // [OUT_F, IN_F]
    const float* __restrict__ buf_bias,   // [OUT_F]
    const float* __restrict__ rng,        // [256]
    const float* __restrict__ acc,        // [1, OUT_F]
    const float* __restrict__ acc_bound,  // [1]
    const int*   __restrict__ rng_wght_idx,     // [OUT_F, IN_F] int32 (jax x64 off)
    const int*   __restrict__ rng_bias_idx,     // [OUT_F]
    const int*   __restrict__ rng_wght_idx_inv, // [OUT_F, IN_F]
    float*       __restrict__ out)        // [1, OUT_F]
{
    __shared__ float s_rng[256];
    __shared__ float s_x[IN_F];
    __shared__ float s_red[NTHREADS / 32];

    const int tid = threadIdx.x;

    if (tid < 256) s_rng[tid] = rng[tid];
    #pragma unroll
    for (int i = tid; i < IN_F; i += NTHREADS) s_x[i] = x[i];
    __syncthreads();

    const int j = blockIdx.x;
    const size_t row = (size_t)j * IN_F;
    const float4* wrow = (const float4*)(buf_wght        + row);
    const int4*   iwr  = (const int4*)  (rng_wght_idx     + row);
    const int4*   ivr  = (const int4*)  (rng_wght_idx_inv + row);

    int sum = 0;
    // IN_F/4 = 1024 vec4 elements, NTHREADS=256 -> 4 iterations
    #pragma unroll
    for (int v = tid; v < IN_F / 4; v += NTHREADS) {
        float4 w  = __ldg(wrow + v);
        int4   ki = __ldg(iwr + v);
        int4   kv = __ldg(ivr + v);
        const float* sx = s_x + 4 * v;

        sum += (sx[0] > 0.5f) ? (w.x >= s_rng[ki.x & 255]) : (w.x < s_rng[kv.x & 255]);
        sum += (sx[1] > 0.5f) ? (w.y >= s_rng[ki.y & 255]) : (w.y < s_rng[kv.y & 255]);
        sum += (sx[2] > 0.5f) ? (w.z >= s_rng[ki.z & 255]) : (w.z < s_rng[kv.z & 255]);
        sum += (sx[3] > 0.5f) ? (w.w >= s_rng[ki.w & 255]) : (w.w < s_rng[kv.w & 255]);
    }

    #pragma unroll
    for (int off = 16; off > 0; off >>= 1)
        sum += __shfl_down_sync(0xFFFFFFFFu, sum, off);

    if ((tid & 31) == 0) s_red[tid >> 5] = (float)sum;
    __syncthreads();

    if (tid == 0) {
        float total = 0.0f;
        #pragma unroll
        for (int w = 0; w < NTHREADS / 32; w++) total += s_red[w];
        int kb = __ldg(rng_bias_idx + j) & 255;
        float b_bit = (__ldg(buf_bias + j) >= s_rng[kb]) ? 1.0f : 0.0f;
        float acc_new = acc[j] + total + b_bit;
        out[j] = (acc_new >= acc_bound[0]) ? 1.0f : 0.0f;
    }
}

extern "C" void kernel_launch(void* const* d_in, const int* in_sizes, int n_in,
                              void* d_out, int out_size)
{
    const float* x            = (const float*)d_in[0];
    const float* buf_wght     = (const float*)d_in[1];
    const float* buf_bias     = (const float*)d_in[2];
    const float* rng          = (const float*)d_in[3];
    const float* acc          = (const float*)d_in[4];
    const float* acc_bound    = (const float*)d_in[5];
    const int*   rng_wght_idx     = (const int*)d_in[6];
    const int*   rng_bias_idx     = (const int*)d_in[7];
    const int*   rng_wght_idx_inv = (const int*)d_in[8];
    float* out = (float*)d_out;

    unary_linear_kernel<<<OUT_F, NTHREADS>>>(
        x, buf_wght, buf_bias, rng, acc, acc_bound,
        rng_wght_idx, rng_bias_idx, rng_wght_idx_inv, out);
}

// round 7
// speedup vs baseline: 1.0009x; 1.0009x over previous
#include <cuda_runtime.h>
#include <cstdint>

#define IN_F   4096
#define OUT_F  4096
#define NTHREADS 256

__global__ __launch_bounds__(NTHREADS)
void unary_linear_kernel(
    const float* __restrict__ x,          // [1, IN_F]
    const float* __restrict__ buf_wght,   // [OUT_F, IN_F]
    const float* __restrict__ buf_bias,   // [OUT_F]
    const float* __restrict__ rng,        // [256] == bitrev8 table (computed in regs)
    const float* __restrict__ acc,        // [1, OUT_F]
    const float* __restrict__ acc_bound,  // [1]
    const int*   __restrict__ rng_wght_idx,     // [OUT_F, IN_F] int32
    const int*   __restrict__ rng_bias_idx,     // [OUT_F]
    const int*   __restrict__ rng_wght_idx_inv, // [OUT_F, IN_F]
    float*       __restrict__ out)        // [1, OUT_F]
{
    __shared__ uint32_t s_xb[IN_F / 32];      // x packed to bits: 128 words
    __shared__ float    s_red[NTHREADS / 32];

    const int tid  = threadIdx.x;
    const int lane = tid & 31;

    // pack x into a bitmask: warp w0 handles words w0, w0+8, ...
    #pragma unroll
    for (int w0 = tid >> 5; w0 < IN_F / 32; w0 += NTHREADS / 32) {
        float xv = x[w0 * 32 + lane];
        uint32_t m = __ballot_sync(0xFFFFFFFFu, xv > 0.5f);
        if (lane == 0) s_xb[w0] = m;
    }
    __syncthreads();

    const int j = blockIdx.x;
    const size_t row = (size_t)j * IN_F;
    const float4* wrow = (const float4*)(buf_wght        + row);
    const int4*   iwr  = (const int4*)  (rng_wght_idx     + row);
    const int4*   ivr  = (const int4*)  (rng_wght_idx_inv + row);

    int sum = 0;
    // IN_F/4 = 1024 vec4 elements, 256 threads -> 4 iterations
    #pragma unroll
    for (int it = 0; it < IN_F / (4 * NTHREADS); it++) {
        int v = tid + it * NTHREADS;
        float4 w  = __ldg(wrow + v);
        int4   ki = __ldg(iwr + v);
        int4   kv = __ldg(ivr + v);
        // 4 x-bits for elements 4v..4v+3 (broadcast LDS, conflict-free)
        uint32_t xb = s_xb[v >> 3] >> ((v & 7) * 4);

        // rng[k % 256] == (float)(__brev(k) >> 24)  (8-bit van der Corput)
        {
            uint32_t b = xb & 1u;
            uint32_t r = b ? (__brev((uint32_t)ki.x) >> 24) : (__brev((uint32_t)kv.x) >> 24);
            sum += ((w.x >= (float)r) == (b != 0));
        }
        {
            uint32_t b = (xb >> 1) & 1u;
            uint32_t r = b ? (__brev((uint32_t)ki.y) >> 24) : (__brev((uint32_t)kv.y) >> 24);
            sum += ((w.y >= (float)r) == (b != 0));
        }
        {
            uint32_t b = (xb >> 2) & 1u;
            uint32_t r = b ? (__brev((uint32_t)ki.z) >> 24) : (__brev((uint32_t)kv.z) >> 24);
            sum += ((w.z >= (float)r) == (b != 0));
        }
        {
            uint32_t b = (xb >> 3) & 1u;
            uint32_t r = b ? (__brev((uint32_t)ki.w) >> 24) : (__brev((uint32_t)kv.w) >> 24);
            sum += ((w.w >= (float)r) == (b != 0));
        }
    }

    // warp reduce
    #pragma unroll
    for (int off = 16; off > 0; off >>= 1)
        sum += __shfl_down_sync(0xFFFFFFFFu, sum, off);

    if (lane == 0) s_red[tid >> 5] = (float)sum;
    __syncthreads();

    if (tid == 0) {
        float total = 0.0f;
        #pragma unroll
        for (int w = 0; w < NTHREADS / 32; w++) total += s_red[w];
        uint32_t kb = __brev((uint32_t)__ldg(rng_bias_idx + j)) >> 24;
        float b_bit = (__ldg(buf_bias + j) >= (float)kb) ? 1.0f : 0.0f;
        float acc_new = acc[j] + total + b_bit;
        out[j] = (acc_new >= acc_bound[0]) ? 1.0f : 0.0f;
    }
}

extern "C" void kernel_launch(void* const* d_in, const int* in_sizes, int n_in,
                              void* d_out, int out_size)
{
    const float* x            = (const float*)d_in[0];
    const float* buf_wght     = (const float*)d_in[1];
    const float* buf_bias     = (const float*)d_in[2];
    const float* rng          = (const float*)d_in[3];
    const float* acc          = (const float*)d_in[4];
    const float* acc_bound    = (const float*)d_in[5];
    const int*   rng_wght_idx     = (const int*)d_in[6];
    const int*   rng_bias_idx     = (const int*)d_in[7];
    const int*   rng_wght_idx_inv = (const int*)d_in[8];
    float* out = (float*)d_out;

    unary_linear_kernel<<<OUT_F, NTHREADS>>>(
        x, buf_wght, buf_bias, rng, acc, acc_bound,
        rng_wght_idx, rng_bias_idx, rng_wght_idx_inv, out);
}